// round 6
// baseline (speedup 1.0000x reference)
#include <cuda_runtime.h>
#include <cuda_bf16.h>

// Problem: B=64, L=1024, D=1280
//   pool_len = lengths + 2
//   emb[b,d]  = mean over l < pool_len of prev[b,l,d]
//   x         = relu(emb @ dense_w + dense_b)        [64,1280]
//   out       = x @ cls_w + cls_b                    [64,1]
//
// Inputs (metadata order): prev_result f32[64,1024,1280], lengths i32[64],
//   dense_w f32[1280,1280], dense_b f32[1280], cls_w f32[1280,1], cls_b f32[1]
// Output: f32[64,1] (out_size = 64)

#define Bq   64
#define Lq   1024
#define Dq   1280
#define D4   (Dq/4)          // 320 float4 per row
#define NSEG 16
#define SEGR (Lq/NSEG)       // 64 rows per segment
#define KS   16              // GEMM k-splits
#define KCH  (Dq/KS)         // 80 k per chunk
#define NJ   20              // j tiles of 64
#define JT   64

// scratch (allocation-free: __device__ globals)
__device__ float g_part [Bq * NSEG * Dq];   // pool partial sums  (5.24 MB)
__device__ float g_emb  [Bq * Dq];          // pooled embedding   (0.33 MB)
__device__ float g_xpart[KS * Bq * Dq];     // GEMM k-partials    (5.24 MB)

// ---------------------------------------------------------------------------
// Kernel 1: ragged partial pool. grid(B, NSEG), block 320 threads (float4/col)
// ---------------------------------------------------------------------------
__global__ void __launch_bounds__(D4) pool_kernel(
    const float* __restrict__ prev, const int* __restrict__ lengths)
{
    const int b   = blockIdx.x;
    const int seg = blockIdx.y;
    const int tid = threadIdx.x;

    const int pl = lengths[b] + 2;            // pool_len in [2, 1023]
    const int l0 = seg * SEGR;
    const int l1 = min(l0 + SEGR, pl);
    const int n  = l1 - l0;

    float4 a0 = make_float4(0.f, 0.f, 0.f, 0.f);
    float4 a1 = a0, a2 = a0, a3 = a0;

    if (n > 0) {
        const float4* __restrict__ p =
            reinterpret_cast<const float4*>(prev) + ((size_t)b * Lq + l0) * D4 + tid;
        int l = 0;
        for (; l + 4 <= n; l += 4) {
            float4 v0 = p[(size_t)(l + 0) * D4];
            float4 v1 = p[(size_t)(l + 1) * D4];
            float4 v2 = p[(size_t)(l + 2) * D4];
            float4 v3 = p[(size_t)(l + 3) * D4];
            a0.x += v0.x; a0.y += v0.y; a0.z += v0.z; a0.w += v0.w;
            a1.x += v1.x; a1.y += v1.y; a1.z += v1.z; a1.w += v1.w;
            a2.x += v2.x; a2.y += v2.y; a2.z += v2.z; a2.w += v2.w;
            a3.x += v3.x; a3.y += v3.y; a3.z += v3.z; a3.w += v3.w;
        }
        for (; l < n; ++l) {
            float4 v = p[(size_t)l * D4];
            a0.x += v.x; a0.y += v.y; a0.z += v.z; a0.w += v.w;
        }
    }
    float4 s;
    s.x = (a0.x + a1.x) + (a2.x + a3.x);
    s.y = (a0.y + a1.y) + (a2.y + a3.y);
    s.z = (a0.z + a1.z) + (a2.z + a3.z);
    s.w = (a0.w + a1.w) + (a2.w + a3.w);

    float4* gp = reinterpret_cast<float4*>(g_part);
    gp[((size_t)b * NSEG + seg) * D4 + tid] = s;
}

// ---------------------------------------------------------------------------
// Kernel 2: reduce partials + divide by pool_len. grid(B), block 320
// ---------------------------------------------------------------------------
__global__ void __launch_bounds__(D4) reduce_kernel(const int* __restrict__ lengths)
{
    const int b   = blockIdx.x;
    const int tid = threadIdx.x;
    const float4* gp = reinterpret_cast<const float4*>(g_part);

    float4 s = make_float4(0.f, 0.f, 0.f, 0.f);
#pragma unroll
    for (int seg = 0; seg < NSEG; ++seg) {
        float4 v = gp[((size_t)b * NSEG + seg) * D4 + tid];
        s.x += v.x; s.y += v.y; s.z += v.z; s.w += v.w;
    }
    const float inv = 1.0f / (float)(lengths[b] + 2);
    s.x *= inv; s.y *= inv; s.z *= inv; s.w *= inv;

    reinterpret_cast<float4*>(g_emb)[(size_t)b * D4 + tid] = s;
}

// ---------------------------------------------------------------------------
// Kernel 3: k-split GEMM partials. grid(NJ, KS), block 128.
// x_part[ky][b][j0+j] = sum_{k in chunk} emb[b][k] * W[k][j0+j]
// per thread: 4 b (stride 16) x 8 j -> 32 fp32 accumulators
// ---------------------------------------------------------------------------
__global__ void __launch_bounds__(128) gemm_kernel(const float* __restrict__ W)
{
    __shared__ __align__(16) float sE[KCH][JT];  // emb[k][b] transposed, 20 KB
    __shared__ __align__(16) float sW[KCH][JT];  // W[k][j tile],          20 KB

    const int tid = threadIdx.x;
    const int j0  = blockIdx.x * JT;
    const int k0  = blockIdx.y * KCH;
    const int ky  = blockIdx.y;

    // stage emb (transposed) and W tile
    for (int i = tid; i < JT * KCH; i += 128) {
        int b  = i & 63;
        int kk = i >> 6;
        sE[kk][b] = g_emb[(size_t)b * Dq + k0 + kk];
    }
    for (int i = tid; i < JT * KCH; i += 128) {
        int j  = i & 63;
        int kk = i >> 6;
        sW[kk][j] = W[(size_t)(k0 + kk) * Dq + j0 + j];
    }
    __syncthreads();

    const int tb = tid & 15;        // b group (16)
    const int tj = tid >> 4;        // j group (8), 8 j each

    float acc[4][8];
#pragma unroll
    for (int i = 0; i < 4; ++i)
#pragma unroll
        for (int j = 0; j < 8; ++j) acc[i][j] = 0.f;

#pragma unroll 4
    for (int kk = 0; kk < KCH; ++kk) {
        float e0 = sE[kk][tb];
        float e1 = sE[kk][tb + 16];
        float e2 = sE[kk][tb + 32];
        float e3 = sE[kk][tb + 48];
        float4 w0 = *reinterpret_cast<const float4*>(&sW[kk][tj * 8]);
        float4 w1 = *reinterpret_cast<const float4*>(&sW[kk][tj * 8 + 4]);
        float wv[8] = {w0.x, w0.y, w0.z, w0.w, w1.x, w1.y, w1.z, w1.w};
        float ev[4] = {e0, e1, e2, e3};
#pragma unroll
        for (int i = 0; i < 4; ++i)
#pragma unroll
            for (int j = 0; j < 8; ++j)
                acc[i][j] += ev[i] * wv[j];
    }

#pragma unroll
    for (int i = 0; i < 4; ++i) {
        int bb = tb + 16 * i;
        float* dst = &g_xpart[((size_t)ky * Bq + bb) * Dq + j0 + tj * 8];
        float4 o0 = make_float4(acc[i][0], acc[i][1], acc[i][2], acc[i][3]);
        float4 o1 = make_float4(acc[i][4], acc[i][5], acc[i][6], acc[i][7]);
        *reinterpret_cast<float4*>(dst)     = o0;
        *reinterpret_cast<float4*>(dst + 4) = o1;
    }
}

// ---------------------------------------------------------------------------
// Kernel 4: reduce k-partials, +bias, relu, dot with cls_w, +cls_b.
// grid(B), block 320 (10 warps)
// ---------------------------------------------------------------------------
__global__ void __launch_bounds__(D4) final_kernel(
    const float* __restrict__ dense_b,
    const float* __restrict__ cls_w,
    const float* __restrict__ cls_b,
    float* __restrict__ out)
{
    const int b   = blockIdx.x;
    const int tid = threadIdx.x;

    float4 s = reinterpret_cast<const float4*>(dense_b)[tid];
    const float4* xp = reinterpret_cast<const float4*>(g_xpart);
#pragma unroll
    for (int ks = 0; ks < KS; ++ks) {
        float4 v = xp[((size_t)ks * Bq + b) * D4 + tid];
        s.x += v.x; s.y += v.y; s.z += v.z; s.w += v.w;
    }
    s.x = fmaxf(s.x, 0.f); s.y = fmaxf(s.y, 0.f);
    s.z = fmaxf(s.z, 0.f); s.w = fmaxf(s.w, 0.f);

    float4 w = reinterpret_cast<const float4*>(cls_w)[tid];
    float part = s.x * w.x + s.y * w.y + s.z * w.z + s.w * w.w;

    // block reduction: 10 warps
    __shared__ float red[10];
#pragma unroll
    for (int o = 16; o > 0; o >>= 1)
        part += __shfl_down_sync(0xffffffffu, part, o);
    if ((tid & 31) == 0) red[tid >> 5] = part;
    __syncthreads();
    if (tid == 0) {
        float t = 0.f;
#pragma unroll
        for (int i = 0; i < 10; ++i) t += red[i];
        out[b] = t + cls_b[0];
    }
}

// ---------------------------------------------------------------------------
extern "C" void kernel_launch(void* const* d_in, const int* in_sizes, int n_in,
                              void* d_out, int out_size)
{
    const float* prev    = (const float*)d_in[0];
    const int*   lengths = (const int*)  d_in[1];
    const float* dense_w = (const float*)d_in[2];
    const float* dense_b = (const float*)d_in[3];
    const float* cls_w   = (const float*)d_in[4];
    const float* cls_b   = (const float*)d_in[5];
    float*       out     = (float*)d_out;

    pool_kernel  <<<dim3(Bq, NSEG), D4>>>(prev, lengths);
    reduce_kernel<<<Bq, D4>>>(lengths);
    gemm_kernel  <<<dim3(NJ, KS), 128>>>(dense_w);
    final_kernel <<<Bq, D4>>>(dense_b, cls_w, cls_b, out);
}